// round 9
// baseline (speedup 1.0000x reference)
#include <cuda_runtime.h>
#include <cuda_fp16.h>
#include <math.h>
#include <stdint.h>

#define T_CTX 100000
#define H 256

// ---- Persistent GEMM: CTA 128x256 tile, 16 warps (4 row x 4 col), B resident ----
#define TILE_M 128
#define NT ((T_CTX + TILE_M - 1) / TILE_M)       // 782 tiles
#define GRID 148                                 // persistent CTAs (1/SM)
#define NTHR 512
#define KT 64                                    // K chunk
#define NCH (H / KT)                             // 4
#define ASTR 72                                  // fp16 row stride (conflict-free, proven)
#define ABUF_H (TILE_M * ASTR)                   // 9216 halves per A chunk buffer
#define BBUF_H (H * ASTR)                        // 18432 halves per B chunk
// smem: B[4][256][72] + A[4][128][72] + red[4][128]f + at_s[128]f + ctc[2][256]f
#define SMEM_GEMM ((4 * BBUF_H + 4 * ABUF_H) * 2 + (4 * TILE_M + TILE_M + 2 * H) * 4) // 225792

// ---- softmax ----
#define SM_BLOCKS 98

// Scratch (static device globals: allocation-free per harness rules)
__device__ float g_At[T_CTX];
__device__ float g_proj[H];
__device__ __half g_WmTh[H * H];                 // Wm transposed, fp16(rn)
__device__ float g_lse;
__device__ float g_sm_m[SM_BLOCKS];
__device__ float g_sm_s[SM_BLOCKS];
__device__ float g_ct1[GRID][H];                 // per-CTA Σ At[t]·M[t,h]
__device__ float g_cs1[GRID][H];                 // per-CTA Σ M[t,h]

// ===========================================================================
// helpers
// ===========================================================================
__device__ __forceinline__ float tanh_fast(float x) {
    float y;
    asm("tanh.approx.f32 %0, %1;" : "=f"(y) : "f"(x));
    return y;
}
__device__ __forceinline__ uint32_t smem_u32(const void* p) {
    uint32_t a;
    asm("{ .reg .u64 t; cvta.to.shared.u64 t, %1; cvt.u32.u64 %0, t; }" : "=r"(a) : "l"(p));
    return a;
}
__device__ __forceinline__ void cp16(uint32_t dst, const void* src) {
    asm volatile("cp.async.cg.shared.global [%0], [%1], 16;" :: "r"(dst), "l"(src) : "memory");
}
__device__ __forceinline__ void cp_commit() {
    asm volatile("cp.async.commit_group;" ::: "memory");
}
__device__ __forceinline__ void ldsm4(uint32_t& r0, uint32_t& r1, uint32_t& r2, uint32_t& r3,
                                      uint32_t addr) {
    asm volatile("ldmatrix.sync.aligned.m8n8.x4.shared.b16 {%0,%1,%2,%3}, [%4];"
                 : "=r"(r0), "=r"(r1), "=r"(r2), "=r"(r3) : "r"(addr));
}
__device__ __forceinline__ void mma_f16(float d[4], const uint32_t a[4], const uint32_t b[2]) {
    asm volatile(
        "mma.sync.aligned.m16n8k16.row.col.f32.f16.f16.f32 "
        "{%0,%1,%2,%3}, {%4,%5,%6,%7}, {%8,%9}, {%0,%1,%2,%3};"
        : "+f"(d[0]), "+f"(d[1]), "+f"(d[2]), "+f"(d[3])
        : "r"(a[0]), "r"(a[1]), "r"(a[2]), "r"(a[3]), "r"(b[0]), "r"(b[1]));
}

// ===========================================================================
// proj = hc @ W1^T  (tiny)
// ===========================================================================
__global__ void proj_kernel(const float* __restrict__ hc, const float* __restrict__ W1) {
    int j = threadIdx.x;
    float s = 0.f;
#pragma unroll 8
    for (int k = 0; k < H; ++k) s = fmaf(hc[k], W1[j * H + k], s);
    g_proj[j] = s;
}

// ===========================================================================
// WmTh[n][k] = f16(Wm[k][n])
// ===========================================================================
__global__ void transpose_kernel(const float* __restrict__ Wm) {
    __shared__ float t[32][33];
    int bx = blockIdx.x & 7, by = blockIdx.x >> 3;
    int x = bx * 32 + threadIdx.x;
#pragma unroll
    for (int j = 0; j < 4; ++j) {
        int y = by * 32 + threadIdx.y + j * 8;
        t[threadIdx.y + j * 8][threadIdx.x] = Wm[y * H + x];
    }
    __syncthreads();
    int x2 = by * 32 + threadIdx.x;
#pragma unroll
    for (int j = 0; j < 4; ++j) {
        int y2 = bx * 32 + threadIdx.y + j * 8;
        g_WmTh[y2 * H + x2] = __float2half_rn(t[threadIdx.x][threadIdx.y + j * 8]);
    }
}

// ===========================================================================
// Persistent fused GEMM + tanh + V-dot + ct partial accumulation.
// ===========================================================================
__global__ void __launch_bounds__(NTHR, 1)
gemm_tanh_mma(const float* __restrict__ A,      // inputs T x H (f32)
              const float* __restrict__ V) {    // H
    extern __shared__ __half smh[];
    __half* Bs = smh;                            // [4][H][ASTR]  resident
    __half* As = smh + 4 * BBUF_H;               // [4][TILE_M][ASTR]
    float* red  = (float*)(smh + 4 * BBUF_H + 4 * ABUF_H);  // [4][TILE_M]
    float* at_s = red + 4 * TILE_M;              // [TILE_M]
    float* ctc  = at_s + TILE_M;                 // [2][H]
    const uint32_t as_u = smem_u32(As);
    const uint32_t bs_u = smem_u32(Bs);

    const int tid = threadIdx.x;
    const int wid = tid >> 5;
    const int lane = tid & 31;
    const int g = lane >> 2;
    const int t = lane & 3;
    const int rg = wid >> 2;          // row group (0..3): rows rg*32..
    const int wc = wid & 3;           // col group (0..3): cols wc*64..
    const int bid = blockIdx.x;

    // ---- B: load ALL 4 chunks once (resident) ----
    {
#pragma unroll
        for (int ch = 0; ch < NCH; ++ch) {
            const int k0 = ch * KT;
#pragma unroll
            for (int i = 0; i < 4; ++i) {
                int idx = tid + i * NTHR;
                int n = idx >> 3;                 // 0..255
                int c8 = (idx & 7) * 8;
                cp16(bs_u + (uint32_t)(ch * BBUF_H + n * ASTR + c8) * 2,
                     g_WmTh + (size_t)n * H + k0 + c8);
            }
        }
        cp_commit();
    }

    // ldmatrix lane-address bases (bytes)
    uint32_t a_lm[2], b_lm[4];
#pragma unroll
    for (int mt = 0; mt < 2; ++mt)
        a_lm[mt] = as_u + 2u * ((uint32_t)(rg * 32 + mt * 16 + (lane & 7) +
                                ((lane >> 3) & 1) * 8) * ASTR + ((lane >> 4) & 1) * 8);
#pragma unroll
    for (int np = 0; np < 4; ++np)
        b_lm[np] = bs_u + 2u * ((uint32_t)(wc * 64 + np * 16 + (lane & 7) +
                                ((lane >> 4) & 1) * 8) * ASTR + ((lane >> 3) & 1) * 8);

    float4 pa[4];                     // A prefetch regs (one chunk: 4 float4/thread)
    // epilogue-2 persistent accumulators (col = tid&255, row-half = tid>>8)
    const int c_ct = tid & 255;
    const int half_ct = tid >> 8;
    float ct_s1 = 0.f, ct_s2 = 0.f;

    auto ldgA = [&](int trow0, int ch) {
        const int k0 = ch * KT;
#pragma unroll
        for (int i = 0; i < 4; ++i) {
            int idx = tid + i * NTHR;
            int r = idx >> 4;                  // 0..127
            int c = (idx & 15) * 4;
            int grow = trow0 + r;
            pa[i] = (grow < T_CTX)
                ? *reinterpret_cast<const float4*>(&A[(size_t)grow * H + k0 + c])
                : make_float4(0.f, 0.f, 0.f, 0.f);
        }
    };
    auto stsA = [&](int buf) {
#pragma unroll
        for (int i = 0; i < 4; ++i) {
            int idx = tid + i * NTHR;
            int r = idx >> 4;
            int c = (idx & 15) * 4;
            *reinterpret_cast<__half2*>(&As[buf * ABUF_H + r * ASTR + c]) =
                __floats2half2_rn(pa[i].x, pa[i].y);
            *reinterpret_cast<__half2*>(&As[buf * ABUF_H + r * ASTR + c + 2]) =
                __floats2half2_rn(pa[i].z, pa[i].w);
        }
    };

    float acc[2][8][4];

    // ---- prologue: first tile's chunk0 into regs; wait for B ----
    int tile = bid;
    if (tile < NT) ldgA(tile * TILE_M, 0);
    asm volatile("cp.async.wait_group 0;" ::: "memory");
    __syncthreads();

    // ---- persistent tile loop ----
    for (; tile < NT; tile += GRID) {
        const int row0 = tile * TILE_M;
#pragma unroll
        for (int mt = 0; mt < 2; ++mt)
#pragma unroll
            for (int nt = 0; nt < 8; ++nt)
#pragma unroll
                for (int r = 0; r < 4; ++r) acc[mt][nt][r] = 0.f;

        auto compute = [&](int ch) {
            const uint32_t aoff = (uint32_t)ch * (ABUF_H * 2);
            const uint32_t boff = (uint32_t)ch * (BBUF_H * 2);
#pragma unroll
            for (int ks = 0; ks < 4; ++ks) {
                const uint32_t koff = ks * 32;
                uint32_t bf[8][2];
#pragma unroll
                for (int np = 0; np < 4; ++np)
                    ldsm4(bf[2 * np][0], bf[2 * np][1], bf[2 * np + 1][0], bf[2 * np + 1][1],
                          b_lm[np] + boff + koff);
#pragma unroll
                for (int mt = 0; mt < 2; ++mt) {
                    uint32_t af[4];
                    ldsm4(af[0], af[1], af[2], af[3], a_lm[mt] + aoff + koff);
#pragma unroll
                    for (int nt = 0; nt < 8; ++nt)
                        mma_f16(acc[mt][nt], af, bf[nt]);
                }
            }
        };

        // pipeline: ph holds A(tile, ch) at top of each step
        stsA(0); ldgA(row0, 1); __syncthreads();
        compute(0); stsA(1); ldgA(row0, 2); __syncthreads();
        compute(1); stsA(2); ldgA(row0, 3); __syncthreads();
        compute(2); stsA(3);
        if (tile + GRID < NT) ldgA((tile + GRID) * TILE_M, 0);  // next tile ch0
        __syncthreads();
        compute(3);

        // --- epilogue 1: tanh + V-dot ---
        float p[4] = {0.f, 0.f, 0.f, 0.f};
#pragma unroll
        for (int nt = 0; nt < 8; ++nt) {
            int cn = wc * 64 + nt * 8 + t * 2;
            float v0 = V[cn],      v1 = V[cn + 1];
            float q0 = g_proj[cn], q1 = g_proj[cn + 1];
#pragma unroll
            for (int mt = 0; mt < 2; ++mt) {
                p[mt * 2 + 0] = fmaf(tanh_fast(acc[mt][nt][0] + q0), v0,
                                fmaf(tanh_fast(acc[mt][nt][1] + q1), v1, p[mt * 2 + 0]));
                p[mt * 2 + 1] = fmaf(tanh_fast(acc[mt][nt][2] + q0), v0,
                                fmaf(tanh_fast(acc[mt][nt][3] + q1), v1, p[mt * 2 + 1]));
            }
        }
#pragma unroll
        for (int j = 0; j < 4; ++j) {
            p[j] += __shfl_xor_sync(0xffffffffu, p[j], 1);
            p[j] += __shfl_xor_sync(0xffffffffu, p[j], 2);
        }
        if (t == 0) {
#pragma unroll
            for (int mt = 0; mt < 2; ++mt)
#pragma unroll
                for (int h = 0; h < 2; ++h)
                    red[wc * TILE_M + rg * 32 + mt * 16 + h * 8 + g] = p[mt * 2 + h];
        }
        __syncthreads();
        if (tid < TILE_M) {
            float s = ((red[tid] + red[TILE_M + tid]) +
                       (red[2 * TILE_M + tid] + red[3 * TILE_M + tid]));
            at_s[tid] = s;
            int grow = row0 + tid;
            if (grow < T_CTX) g_At[grow] = s;
        }
        __syncthreads();

        // --- epilogue 2: accumulate ct partials (rows half_ct*64 .. +63) ---
        {
            const __half* col = As + (c_ct >> 6) * ABUF_H + (c_ct & 63);
            const int r0 = half_ct * 64;
#pragma unroll 8
            for (int r = r0; r < r0 + 64; ++r) {
                float f = __half2float(col[r * ASTR]);
                ct_s1 = fmaf(at_s[r], f, ct_s1);
                ct_s2 += f;
            }
        }
        __syncthreads();   // A buffers free for next tile's stsA(0)
    }

    // ---- final: combine the two row-halves, write per-CTA partials ----
    if (half_ct == 1) {
        ctc[c_ct] = ct_s1;
        ctc[H + c_ct] = ct_s2;
    }
    __syncthreads();
    if (half_ct == 0) {
        g_ct1[bid][c_ct] = ct_s1 + ctc[c_ct];
        g_cs1[bid][c_ct] = ct_s2 + ctc[H + c_ct];
    }
}

// ===========================================================================
// Two-stage logsumexp over At
// ===========================================================================
__global__ void softmax_part_kernel() {
    __shared__ float wred[32];
    const int tid = threadIdx.x;
    const int lane = tid & 31;
    const int wid = tid >> 5;
    const int tt = blockIdx.x * 1024 + tid;

    float v = (tt < T_CTX) ? g_At[tt] : -1e30f;
    float m = v;
#pragma unroll
    for (int s = 16; s > 0; s >>= 1) m = fmaxf(m, __shfl_xor_sync(~0u, m, s));
    if (lane == 0) wred[wid] = m;
    __syncthreads();
    if (wid == 0) {
        float mm = wred[lane];
#pragma unroll
        for (int s = 16; s > 0; s >>= 1) mm = fmaxf(mm, __shfl_xor_sync(~0u, mm, s));
        wred[lane] = mm;
    }
    __syncthreads();
    const float bm = wred[0];

    float sum = expf(v - bm);
#pragma unroll
    for (int s = 16; s > 0; s >>= 1) sum += __shfl_xor_sync(~0u, sum, s);
    __syncthreads();
    if (lane == 0) wred[wid] = sum;
    __syncthreads();
    if (tid == 0) {
        float S = 0.f;
#pragma unroll
        for (int i = 0; i < 32; ++i) S += wred[i];   // fixed order
        g_sm_m[blockIdx.x] = bm;
        g_sm_s[blockIdx.x] = S;
    }
}

__global__ void softmax_final_kernel() {
    const int lane = threadIdx.x;        // 32
    float m = -1e30f;
    for (int i = lane; i < SM_BLOCKS; i += 32) m = fmaxf(m, g_sm_m[i]);
#pragma unroll
    for (int s = 16; s > 0; s >>= 1) m = fmaxf(m, __shfl_xor_sync(~0u, m, s));
    float S = 0.f;
    for (int i = lane; i < SM_BLOCKS; i += 32) S += g_sm_s[i] * expf(g_sm_m[i] - m);
#pragma unroll
    for (int s = 16; s > 0; s >>= 1) S += __shfl_xor_sync(~0u, S, s);
    if (lane == 0) g_lse = m + logf(S);
}

// ===========================================================================
// alphat = At - lse
// ===========================================================================
__global__ void alpha_kernel(float* __restrict__ out_alpha) {
    int t = blockIdx.x * 1024 + threadIdx.x;
    if (t < T_CTX) out_alpha[t] = g_At[t] - g_lse;
}

// ===========================================================================
// ct final: sum 148 per-CTA partials (4 slices x 256 cols, fixed order)
// ===========================================================================
__global__ void __launch_bounds__(1024)
ctfinal_kernel(float* __restrict__ out_ct) {
    __shared__ float sm1[4][H];
    __shared__ float sm2[4][H];
    const int c = threadIdx.x & 255;
    const int js = threadIdx.x >> 8;     // 0..3
    float s1 = 0.f, s2 = 0.f;
    const int b0 = js * 37;
    const int b1 = min(b0 + 37, GRID);
    for (int b = b0; b < b1; ++b) {      // fixed order
        s1 += g_ct1[b][c];
        s2 += g_cs1[b][c];
    }
    sm1[js][c] = s1;
    sm2[js][c] = s2;
    __syncthreads();
    if (js == 0) {
        float t1 = ((sm1[0][c] + sm1[1][c]) + (sm1[2][c] + sm1[3][c]));
        float t2 = ((sm2[0][c] + sm2[1][c]) + (sm2[2][c] + sm2[3][c]));
        out_ct[c] = t1 - g_lse * t2;
    }
}

// ===========================================================================
extern "C" void kernel_launch(void* const* d_in, const int* in_sizes, int n_in,
                              void* d_out, int out_size) {
    const float* inputs = (const float*)d_in[0];   // (T, H)
    const float* hc     = (const float*)d_in[1];   // (1, H)
    const float* Wm     = (const float*)d_in[2];   // (H, H)
    const float* V      = (const float*)d_in[3];   // (H, 1)
    const float* W1     = (const float*)d_in[4];   // (H, H)
    float* out = (float*)d_out;                    // [alphat (T) | ct (H)]

    static int smem_set = 0;
    if (!smem_set) {
        cudaFuncSetAttribute(gemm_tanh_mma,
                             cudaFuncAttributeMaxDynamicSharedMemorySize, SMEM_GEMM);
        smem_set = 1;
    }

    proj_kernel<<<1, 256>>>(hc, W1);
    transpose_kernel<<<64, dim3(32, 8)>>>(Wm);
    gemm_tanh_mma<<<GRID, NTHR, SMEM_GEMM>>>(inputs, V);
    softmax_part_kernel<<<SM_BLOCKS, 1024>>>();
    softmax_final_kernel<<<1, 32>>>();
    alpha_kernel<<<(T_CTX + 1023) / 1024, 1024>>>(out);
    ctfinal_kernel<<<1, 1024>>>(out + T_CTX);
}